// round 6
// baseline (speedup 1.0000x reference)
#include <cuda_runtime.h>
#include <cuda_fp16.h>
#include <cstdint>

// ---------------- problem constants ----------------
#define B_WIN 4096
#define NTOK  49
#define DIM   192
#define HEADS 6
#define HD    32
#define MTOT  (B_WIN * NTOK)            // 200704 rows
#define QKV_N (3 * DIM)                 // 576
#define SCALE 0.17677669529663687f      // 1/sqrt(32)

// ---------------- scratch (device globals: no allocs allowed) ----------------
__device__ __half g_wqkvh [QKV_N * DIM];                           // qkv_w half
__device__ __half g_wprojh[DIM * DIM];                             // proj_w half
__device__ __half g_qkvh  [(size_t)3 * B_WIN * HEADS * NTOK * HD]; // [3,B,H,49,32]
__device__ __half g_attnh [(size_t)MTOT * DIM];                    // attn out half
__device__ float  g_bias  [HEADS * 2404];                          // padded per-head bias

// ---------------- helpers ----------------
__device__ __forceinline__ unsigned packh2(float a, float b) {
    __half2 h = __floats2half2_rn(a, b);
    return *reinterpret_cast<unsigned*>(&h);
}

__device__ __forceinline__ void mma16(float* c, const unsigned* a, const unsigned* b) {
    asm volatile(
        "mma.sync.aligned.m16n8k16.row.col.f32.f16.f16.f32 "
        "{%0,%1,%2,%3},{%4,%5,%6,%7},{%8,%9},{%0,%1,%2,%3};\n"
        : "+f"(c[0]), "+f"(c[1]), "+f"(c[2]), "+f"(c[3])
        : "r"(a[0]), "r"(a[1]), "r"(a[2]), "r"(a[3]), "r"(b[0]), "r"(b[1]));
}

// ---------------- prepass: weight fp32 -> half ----------------
template <int DST>
__global__ void cvt_kernel(const float* __restrict__ src, int n4) {
    int i = blockIdx.x * blockDim.x + threadIdx.x;
    if (i >= n4) return;
    float4 v = reinterpret_cast<const float4*>(src)[i];
    uint2 u; u.x = packh2(v.x, v.y); u.y = packh2(v.z, v.w);
    __half* dst = (DST == 1) ? g_wqkvh : g_wprojh;
    reinterpret_cast<uint2*>(dst)[i] = u;
}

// ---------------- bias gather (padded stride 2404) ----------------
__global__ void bias_kernel(const float* __restrict__ bias_table,
                            const int* __restrict__ rel_index) {
    int idx = blockIdx.x * blockDim.x + threadIdx.x;
    if (idx < HEADS * NTOK * NTOK) {
        int h  = idx / (NTOK * NTOK);
        int ij = idx - h * (NTOK * NTOK);
        g_bias[h * 2404 + ij] = bias_table[rel_index[ij] * HEADS + h];
    }
}

// ---------------- GEMM: C[M,Ntot] = A[M,192] @ W[Ntot,192]^T + bias ----------------
// Block tile 128x192, 6 warps (2m x 3n), warp tile 64x64, K=192 fully smem-resident.
// MODE 0: A = x (fp32, converted in staging), W = g_wqkvh -> scatter half into g_qkvh
// MODE 1: A = g_attnh (half), W = g_wprojh -> fp32 out (+proj_b)
#define G_SMEM_BYTES ((12800 + 19200) * 4)

template <int MODE>
__global__ void __launch_bounds__(192) gemm_kernel(const float* __restrict__ Ax,
                                                   const float* __restrict__ bias,
                                                   float* __restrict__ Cout) {
    extern __shared__ __align__(16) unsigned sh[];
    unsigned* As = sh;            // 128 rows x 100 words (96 data + 4 pad)
    unsigned* Bs = sh + 12800;    // 192 rows x 100 words

    const __half* W = (MODE == 0) ? g_wqkvh : g_wprojh;

    const int tid = threadIdx.x;
    const int w = tid / 32, lane = tid & 31, g = lane >> 2, t = lane & 3;
    const int wm = (w / 3) * 64, wn = (w % 3) * 64;
    const int m0 = blockIdx.y * 128;
    const int n0 = blockIdx.x * 192;

    // ---- stage A (full K=192) ----
    if (MODE == 0) {
        for (int i = tid; i < 6144; i += 192) {            // 128 rows x 48 float4
            const int r = i / 48, c = i - r * 48;
            float4 v = *reinterpret_cast<const float4*>(Ax + (size_t)(m0 + r) * 192 + c * 4);
            uint2 u; u.x = packh2(v.x, v.y); u.y = packh2(v.z, v.w);
            *reinterpret_cast<uint2*>(&As[r * 100 + c * 2]) = u;
        }
    } else {
        for (int i = tid; i < 3072; i += 192) {            // 128 rows x 24 uint4
            const int r = i / 24, c = i - r * 24;
            uint4 u = *reinterpret_cast<const uint4*>(g_attnh + (size_t)(m0 + r) * 192 + c * 8);
            *reinterpret_cast<uint4*>(&As[r * 100 + c * 4]) = u;
        }
    }
    // ---- stage B: 192 rows x 192 halves ----
    for (int i = tid; i < 4608; i += 192) {                // 192 rows x 24 uint4
        const int r = i / 24, c = i - r * 24;
        uint4 u = *reinterpret_cast<const uint4*>(W + (size_t)(n0 + r) * 192 + c * 8);
        *reinterpret_cast<uint4*>(&Bs[r * 100 + c * 4]) = u;
    }
    __syncthreads();

    float acc[4][8][4];
#pragma unroll
    for (int mf = 0; mf < 4; mf++)
#pragma unroll
        for (int nf = 0; nf < 8; nf++)
#pragma unroll
            for (int v = 0; v < 4; v++) acc[mf][nf][v] = 0.f;

    // ---- mainloop: 12 k16 steps, K resident ----
#pragma unroll
    for (int s = 0; s < 12; s++) {
        const int kw = s * 8;
        unsigned a[4][4];
#pragma unroll
        for (int mf = 0; mf < 4; mf++) {
            const int base = (wm + mf * 16 + g) * 100 + kw + t;
            a[mf][0] = As[base];
            a[mf][1] = As[base + 800];
            a[mf][2] = As[base + 4];
            a[mf][3] = As[base + 804];
        }
#pragma unroll
        for (int nf = 0; nf < 8; nf++) {
            const int bb = (wn + nf * 8 + g) * 100 + kw + t;
            unsigned bf[2] = { Bs[bb], Bs[bb + 4] };
#pragma unroll
            for (int mf = 0; mf < 4; mf++) mma16(acc[mf][nf], a[mf], bf);
        }
    }

    // ---- epilogue ----
#pragma unroll
    for (int mf = 0; mf < 4; mf++) {
        const int ma = m0 + wm + mf * 16 + g;
        const int mb = ma + 8;
        const int wa = ma / 49, ta = ma - wa * 49;
        const int wb = mb / 49, tb = mb - wb * 49;
#pragma unroll
        for (int nf = 0; nf < 8; nf++) {
            const int gc = n0 + wn + nf * 8 + 2 * t;
            float2 bb = __ldg(reinterpret_cast<const float2*>(bias + gc));
            float v00 = acc[mf][nf][0] + bb.x;
            float v01 = acc[mf][nf][1] + bb.y;
            float v10 = acc[mf][nf][2] + bb.x;
            float v11 = acc[mf][nf][3] + bb.y;
            if (MODE == 0) {
                if (gc < 192) { v00 *= SCALE; v01 *= SCALE; v10 *= SCALE; v11 *= SCALE; }
                const int s2 = gc / 192;
                const int hh = (gc - s2 * 192) >> 5;
                const int d  = gc & 31;
                __half2* pa = reinterpret_cast<__half2*>(
                    g_qkvh + ((((size_t)s2 * B_WIN + wa) * HEADS + hh) * NTOK + ta) * HD + d);
                __half2* pb = reinterpret_cast<__half2*>(
                    g_qkvh + ((((size_t)s2 * B_WIN + wb) * HEADS + hh) * NTOK + tb) * HD + d);
                *pa = __floats2half2_rn(v00, v01);
                *pb = __floats2half2_rn(v10, v11);
            } else {
                *reinterpret_cast<float2*>(Cout + (size_t)ma * DIM + gc) = make_float2(v00, v01);
                *reinterpret_cast<float2*>(Cout + (size_t)mb * DIM + gc) = make_float2(v10, v11);
            }
        }
    }
}

// ---------------- attention: one block per (window-pair, head), 256 threads ----------------
// Per-window region (3712 words): qs 64x20 | ks 64x20 | vs 32x36; Ps reuses [0,2304).
// Shared bias (2404 floats) staged once for both windows.
__global__ void __launch_bounds__(256) attn_kernel() {
    __shared__ __align__(16) unsigned sm[2 * 3712 + 2404];

    const int tid = threadIdx.x;
    const int half_id = tid >> 7;       // window select within pair
    const int wt = tid & 127;

    const int bh2 = blockIdx.x;
    const int h = bh2 % HEADS;
    const int wp = bh2 / HEADS;
    const int b = wp * 2 + half_id;

    unsigned* base = sm + half_id * 3712;
    unsigned* qs = base;
    unsigned* ks = base + 1280;
    unsigned* vs = base + 2560;
    unsigned* Ps = base;
    float* biasf = reinterpret_cast<float*>(sm + 2 * 3712);

    const __half* qg = g_qkvh + ((size_t)b * HEADS + h) * (NTOK * HD);
    const __half* kg = qg + (size_t)B_WIN * HEADS * NTOK * HD;
    const __half* vg = kg + (size_t)B_WIN * HEADS * NTOK * HD;

    // stage q,k row-major (zero-pad rows >= 49); v transposed [dim][token]
    for (int idx = wt; idx < 512; idx += 128) {
        const int r = idx >> 3, c = idx & 7;
        uint2 zq = make_uint2(0u, 0u), zk = zq, zv = zq;
        if (r < NTOK) {
            zq = *reinterpret_cast<const uint2*>(qg + r * 32 + c * 4);
            zk = *reinterpret_cast<const uint2*>(kg + r * 32 + c * 4);
            zv = *reinterpret_cast<const uint2*>(vg + r * 32 + c * 4);
        }
        *reinterpret_cast<uint2*>(&qs[r * 20 + c * 2]) = zq;
        *reinterpret_cast<uint2*>(&ks[r * 20 + c * 2]) = zk;
        const __half* hv = reinterpret_cast<const __half*>(&zv);
        char* vbase = reinterpret_cast<char*>(vs);
#pragma unroll
        for (int u = 0; u < 4; u++) {
            const int d = c * 4 + u;
            *reinterpret_cast<__half*>(vbase + (d * 36 + (r >> 1)) * 4 + (r & 1) * 2) = hv[u];
        }
    }
    // stage bias once for the pair (601 uint4 = 2404 floats)
    for (int i = tid; i < 601; i += 256) {
        uint4 u = *reinterpret_cast<const uint4*>(g_bias + h * 2404 + i * 4);
        *reinterpret_cast<uint4*>(&biasf[i * 4]) = u;
    }
    __syncthreads();

    const int w = wt >> 5, lane = tid & 31, g = lane >> 2, t = lane & 3;
    const int i0 = w * 16 + g, i1 = i0 + 8;

    // ---- S = q @ k^T ----
    float sacc[8][4];
#pragma unroll
    for (int j = 0; j < 8; j++)
#pragma unroll
        for (int v = 0; v < 4; v++) sacc[j][v] = 0.f;

#pragma unroll
    for (int ks2 = 0; ks2 < 2; ks2++) {
        const int kw = ks2 * 8;
        unsigned a[4] = { qs[i0 * 20 + kw + t], qs[i1 * 20 + kw + t],
                          qs[i0 * 20 + kw + t + 4], qs[i1 * 20 + kw + t + 4] };
#pragma unroll
        for (int j = 0; j < 8; j++) {
            unsigned bf[2] = { ks[(j * 8 + g) * 20 + kw + t],
                               ks[(j * 8 + g) * 20 + kw + t + 4] };
            mma16(sacc[j], a, bf);
        }
    }
    __syncthreads();   // all warps done reading qs/ks before Ps overwrite

    // ---- bias + mask + softmax ----
    float mx0 = -1e30f, mx1 = -1e30f;
#pragma unroll
    for (int j = 0; j < 8; j++) {
        const int j0 = j * 8 + 2 * t, j1 = j0 + 1;
        sacc[j][0] = (i0 < 49 && j0 < 49) ? sacc[j][0] + biasf[i0 * 49 + j0] : -1e30f;
        sacc[j][1] = (i0 < 49 && j1 < 49) ? sacc[j][1] + biasf[i0 * 49 + j1] : -1e30f;
        sacc[j][2] = (i1 < 49 && j0 < 49) ? sacc[j][2] + biasf[i1 * 49 + j0] : -1e30f;
        sacc[j][3] = (i1 < 49 && j1 < 49) ? sacc[j][3] + biasf[i1 * 49 + j1] : -1e30f;
        mx0 = fmaxf(mx0, fmaxf(sacc[j][0], sacc[j][1]));
        mx1 = fmaxf(mx1, fmaxf(sacc[j][2], sacc[j][3]));
    }
    mx0 = fmaxf(mx0, __shfl_xor_sync(0xffffffffu, mx0, 1));
    mx0 = fmaxf(mx0, __shfl_xor_sync(0xffffffffu, mx0, 2));
    mx1 = fmaxf(mx1, __shfl_xor_sync(0xffffffffu, mx1, 1));
    mx1 = fmaxf(mx1, __shfl_xor_sync(0xffffffffu, mx1, 2));

    float s0 = 0.f, s1 = 0.f;
#pragma unroll
    for (int j = 0; j < 8; j++) {
        float p0 = __expf(sacc[j][0] - mx0); sacc[j][0] = p0; s0 += p0;
        float p1 = __expf(sacc[j][1] - mx0); sacc[j][1] = p1; s0 += p1;
        float p2 = __expf(sacc[j][2] - mx1); sacc[j][2] = p2; s1 += p2;
        float p3 = __expf(sacc[j][3] - mx1); sacc[j][3] = p3; s1 += p3;
    }
    s0 += __shfl_xor_sync(0xffffffffu, s0, 1);
    s0 += __shfl_xor_sync(0xffffffffu, s0, 2);
    s1 += __shfl_xor_sync(0xffffffffu, s1, 1);
    s1 += __shfl_xor_sync(0xffffffffu, s1, 2);

    // store unnormalized P as half2 (own rows only)
#pragma unroll
    for (int j = 0; j < 8; j++) {
        Ps[i0 * 36 + j * 4 + t] = packh2(sacc[j][0], sacc[j][1]);
        Ps[i1 * 36 + j * 4 + t] = packh2(sacc[j][2], sacc[j][3]);
    }
    __syncwarp();

    // ---- O = P @ V ----
    float oacc[4][4];
#pragma unroll
    for (int nb = 0; nb < 4; nb++)
#pragma unroll
        for (int v = 0; v < 4; v++) oacc[nb][v] = 0.f;

#pragma unroll
    for (int kk = 0; kk < 4; kk++) {
        const int kw = kk * 8;
        unsigned a[4] = { Ps[i0 * 36 + kw + t], Ps[i1 * 36 + kw + t],
                          Ps[i0 * 36 + kw + t + 4], Ps[i1 * 36 + kw + t + 4] };
#pragma unroll
        for (int nb = 0; nb < 4; nb++) {
            unsigned bf[2] = { vs[(nb * 8 + g) * 36 + kw + t],
                               vs[(nb * 8 + g) * 36 + kw + t + 4] };
            mma16(oacc[nb], a, bf);
        }
    }

    const float inv0 = 1.f / s0, inv1 = 1.f / s1;
    if (i0 < 49) {
        __half* obase = g_attnh + ((size_t)b * 49 + i0) * 192 + h * 32;
#pragma unroll
        for (int nb = 0; nb < 4; nb++) {
            const int d0 = nb * 8 + 2 * t;
            *reinterpret_cast<__half2*>(obase + d0) =
                __floats2half2_rn(oacc[nb][0] * inv0, oacc[nb][1] * inv0);
        }
    }
    if (i1 < 49) {
        __half* obase = g_attnh + ((size_t)b * 49 + i1) * 192 + h * 32;
#pragma unroll
        for (int nb = 0; nb < 4; nb++) {
            const int d0 = nb * 8 + 2 * t;
            *reinterpret_cast<__half2*>(obase + d0) =
                __floats2half2_rn(oacc[nb][2] * inv1, oacc[nb][3] * inv1);
        }
    }
}

// ---------------- launch ----------------
extern "C" void kernel_launch(void* const* d_in, const int* in_sizes, int n_in,
                              void* d_out, int out_size) {
    const float* x          = (const float*)d_in[0];
    const float* qkv_w      = (const float*)d_in[1];
    const float* qkv_b      = (const float*)d_in[2];
    const float* proj_w     = (const float*)d_in[3];
    const float* proj_b     = (const float*)d_in[4];
    const float* bias_table = (const float*)d_in[5];
    const int*   rel_index  = (const int*)d_in[6];
    float* out = (float*)d_out;

    cudaFuncSetAttribute(gemm_kernel<0>, cudaFuncAttributeMaxDynamicSharedMemorySize, G_SMEM_BYTES);
    cudaFuncSetAttribute(gemm_kernel<1>, cudaFuncAttributeMaxDynamicSharedMemorySize, G_SMEM_BYTES);

    cvt_kernel<1><<<(QKV_N * DIM / 4 + 255) / 256, 256>>>(qkv_w, QKV_N * DIM / 4);
    cvt_kernel<2><<<(DIM * DIM / 4 + 255) / 256, 256>>>(proj_w, DIM * DIM / 4);
    bias_kernel<<<(HEADS * NTOK * NTOK + 255) / 256, 256>>>(bias_table, rel_index);

    gemm_kernel<0><<<dim3(QKV_N / 192, MTOT / 128), 192, G_SMEM_BYTES>>>(x, qkv_b, nullptr);
    attn_kernel<<<B_WIN * HEADS / 2, 256>>>();
    gemm_kernel<1><<<dim3(1, MTOT / 128), 192, G_SMEM_BYTES>>>(nullptr, proj_b, out);
}

// round 7
// speedup vs baseline: 1.4542x; 1.4542x over previous
#include <cuda_runtime.h>
#include <cuda_fp16.h>
#include <cstdint>

// ---------------- problem constants ----------------
#define B_WIN 4096
#define NTOK  49
#define DIM   192
#define HEADS 6
#define HD    32
#define MTOT  (B_WIN * NTOK)            // 200704 rows
#define QKV_N (3 * DIM)                 // 576
#define SCALE 0.17677669529663687f      // 1/sqrt(32)

// ---------------- scratch (device globals: no allocs allowed) ----------------
__device__ __half g_xh    [(size_t)MTOT * DIM];                    // x in half
__device__ __half g_wqkvh [QKV_N * DIM];                           // qkv_w half
__device__ __half g_wprojh[DIM * DIM];                             // proj_w half
__device__ __half g_qkvh  [(size_t)3 * B_WIN * HEADS * NTOK * HD]; // [3,B,H,49,32]
__device__ __half g_attnh [(size_t)MTOT * DIM];                    // attn out half
__device__ float  g_bias  [HEADS * 2404];                          // padded per-head bias

// ---------------- helpers ----------------
__device__ __forceinline__ unsigned packh2(float a, float b) {
    __half2 h = __floats2half2_rn(a, b);
    return *reinterpret_cast<unsigned*>(&h);
}

__device__ __forceinline__ void mma16(float* c, const unsigned* a, const unsigned* b) {
    asm volatile(
        "mma.sync.aligned.m16n8k16.row.col.f32.f16.f16.f32 "
        "{%0,%1,%2,%3},{%4,%5,%6,%7},{%8,%9},{%0,%1,%2,%3};\n"
        : "+f"(c[0]), "+f"(c[1]), "+f"(c[2]), "+f"(c[3])
        : "r"(a[0]), "r"(a[1]), "r"(a[2]), "r"(a[3]), "r"(b[0]), "r"(b[1]));
}

__device__ __forceinline__ uint32_t smem_u32(const void* p) {
    uint32_t a;
    asm("{ .reg .u64 t; cvta.to.shared.u64 t, %1; cvt.u32.u64 %0, t; }" : "=r"(a) : "l"(p));
    return a;
}

__device__ __forceinline__ void cpasync16(uint32_t dst, const void* src) {
    asm volatile("cp.async.ca.shared.global [%0], [%1], 16;" :: "r"(dst), "l"(src));
}
#define CP_COMMIT() asm volatile("cp.async.commit_group;" ::: "memory")
#define CP_WAIT(N)  asm volatile("cp.async.wait_group %0;" :: "n"(N) : "memory")

// ---------------- prepass: fp32 -> half converters ----------------
template <int DST>
__global__ void cvt_kernel(const float* __restrict__ src, int n4) {
    int i = blockIdx.x * blockDim.x + threadIdx.x;
    if (i >= n4) return;
    float4 v = reinterpret_cast<const float4*>(src)[i];
    uint2 u; u.x = packh2(v.x, v.y); u.y = packh2(v.z, v.w);
    __half* dst = (DST == 0) ? g_xh : (DST == 1) ? g_wqkvh : g_wprojh;
    reinterpret_cast<uint2*>(dst)[i] = u;
}

// ---------------- bias gather (padded stride 2404) ----------------
__global__ void bias_kernel(const float* __restrict__ bias_table,
                            const int* __restrict__ rel_index) {
    int idx = blockIdx.x * blockDim.x + threadIdx.x;
    if (idx < HEADS * NTOK * NTOK) {
        int h  = idx / (NTOK * NTOK);
        int ij = idx - h * (NTOK * NTOK);
        g_bias[h * 2404 + ij] = bias_table[rel_index[ij] * HEADS + h];
    }
}

// ---------------- GEMM: C[M,Ntot] = A[M,192] @ W[Ntot,192]^T + bias ----------------
// Block tile 128x64, 4 warps (2x2), warp tile 64x32, k-tile 64.
// 2-stage cp.async double-buffered pipeline over the 3 k-tiles.
// Stage layout (words): A 128x36 (=4608) | B 64x36 (=2304); stage size 6912 words.
#define STG_WORDS 6912
#define G_SMEM_BYTES (2 * STG_WORDS * 4)

// stage one k-tile (A: 1024 16B chunks, B: 512) into stage buffer at sbase (byte addr)
__device__ __forceinline__ void stage_tile(uint32_t sbase, const __half* A, const __half* W,
                                           int m0, int n0, int kb, int tid) {
#pragma unroll
    for (int k = 0; k < 8; k++) {
        const int i = tid + k * 128;
        const int r = i >> 3, c = i & 7;
        cpasync16(sbase + (uint32_t)(r * 36 + c * 4) * 4,
                  A + (size_t)(m0 + r) * 192 + kb + c * 8);
    }
#pragma unroll
    for (int k = 0; k < 4; k++) {
        const int i = tid + k * 128;
        const int r = i >> 3, c = i & 7;
        cpasync16(sbase + (uint32_t)(4608 + r * 36 + c * 4) * 4,
                  W + (size_t)(n0 + r) * 192 + kb + c * 8);
    }
}

__device__ __forceinline__ void compute_tile(const unsigned* buf, float acc[4][4][4],
                                             int wm, int wn, int g, int t) {
    const unsigned* As = buf;
    const unsigned* Bs = buf + 4608;
#pragma unroll
    for (int ks = 0; ks < 4; ks++) {
        const int kw = ks * 8;
        unsigned a[4][4], bf[4][2];
#pragma unroll
        for (int mf = 0; mf < 4; mf++) {
            const int base = (wm + mf * 16 + g) * 36 + kw + t;
            a[mf][0] = As[base];
            a[mf][1] = As[base + 8 * 36];
            a[mf][2] = As[base + 4];
            a[mf][3] = As[base + 8 * 36 + 4];
        }
#pragma unroll
        for (int nf = 0; nf < 4; nf++) {
            const int base = (wn + nf * 8 + g) * 36 + kw + t;
            bf[nf][0] = Bs[base];
            bf[nf][1] = Bs[base + 4];
        }
#pragma unroll
        for (int mf = 0; mf < 4; mf++)
#pragma unroll
            for (int nf = 0; nf < 4; nf++) mma16(acc[mf][nf], a[mf], bf[nf]);
    }
}

template <int MODE>
__global__ void __launch_bounds__(128) gemm_kernel(const float* __restrict__ bias,
                                                   float* __restrict__ Cout) {
    extern __shared__ __align__(16) unsigned sh[];
    const uint32_t sb = smem_u32(sh);

    const __half* A = (MODE == 0) ? g_xh : g_attnh;
    const __half* W = (MODE == 0) ? g_wqkvh : g_wprojh;

    const int tid = threadIdx.x;
    const int w = tid >> 5, lane = tid & 31, g = lane >> 2, t = lane & 3;
    const int wm = (w >> 1) * 64, wn = (w & 1) * 32;
    const int m0 = blockIdx.y * 128;
    const int n0 = blockIdx.x * 64;

    float acc[4][4][4];
#pragma unroll
    for (int mf = 0; mf < 4; mf++)
#pragma unroll
        for (int nf = 0; nf < 4; nf++)
#pragma unroll
            for (int v = 0; v < 4; v++) acc[mf][nf][v] = 0.f;

    // prologue: prefetch tiles 0 and 1
    stage_tile(sb,                 A, W, m0, n0, 0,   tid); CP_COMMIT();
    stage_tile(sb + STG_WORDS * 4, A, W, m0, n0, 64,  tid); CP_COMMIT();

    // kt = 0
    CP_WAIT(1); __syncthreads();
    compute_tile(sh, acc, wm, wn, g, t);
    __syncthreads();
    stage_tile(sb, A, W, m0, n0, 128, tid); CP_COMMIT();

    // kt = 1
    CP_WAIT(1); __syncthreads();
    compute_tile(sh + STG_WORDS, acc, wm, wn, g, t);
    __syncthreads();

    // kt = 2
    CP_WAIT(0); __syncthreads();
    compute_tile(sh, acc, wm, wn, g, t);

    // ---- epilogue ----
#pragma unroll
    for (int mf = 0; mf < 4; mf++) {
        const int ma = m0 + wm + mf * 16 + g;
        const int mb = ma + 8;
        const int wa = ma / 49, ta = ma - wa * 49;
        const int wb = mb / 49, tb = mb - wb * 49;
#pragma unroll
        for (int nf = 0; nf < 4; nf++) {
            const int gc = n0 + wn + nf * 8 + 2 * t;
            float2 bb = __ldg(reinterpret_cast<const float2*>(bias + gc));
            float v00 = acc[mf][nf][0] + bb.x;
            float v01 = acc[mf][nf][1] + bb.y;
            float v10 = acc[mf][nf][2] + bb.x;
            float v11 = acc[mf][nf][3] + bb.y;
            if (MODE == 0) {
                if (gc < 192) { v00 *= SCALE; v01 *= SCALE; v10 *= SCALE; v11 *= SCALE; }
                const int s  = gc / 192;
                const int hh = (gc - s * 192) >> 5;
                const int d  = gc & 31;
                __half2* pa = reinterpret_cast<__half2*>(
                    g_qkvh + ((((size_t)s * B_WIN + wa) * HEADS + hh) * NTOK + ta) * HD + d);
                __half2* pb = reinterpret_cast<__half2*>(
                    g_qkvh + ((((size_t)s * B_WIN + wb) * HEADS + hh) * NTOK + tb) * HD + d);
                *pa = __floats2half2_rn(v00, v01);
                *pb = __floats2half2_rn(v10, v11);
            } else {
                *reinterpret_cast<float2*>(Cout + (size_t)ma * DIM + gc) = make_float2(v00, v01);
                *reinterpret_cast<float2*>(Cout + (size_t)mb * DIM + gc) = make_float2(v10, v11);
            }
        }
    }
}

// ---------------- attention: one block per (window-pair, head), 256 threads ----------------
// Per-window region (3712 words): qs 64x20 | ks 64x20 | vs 32x36; Ps reuses [0,2304).
// Shared bias (2404 floats) staged once for both windows.
__global__ void __launch_bounds__(256) attn_kernel() {
    __shared__ __align__(16) unsigned sm[2 * 3712 + 2404];

    const int tid = threadIdx.x;
    const int half_id = tid >> 7;       // window select within pair
    const int wt = tid & 127;

    const int bh2 = blockIdx.x;
    const int h = bh2 % HEADS;
    const int wp = bh2 / HEADS;
    const int b = wp * 2 + half_id;

    unsigned* base = sm + half_id * 3712;
    unsigned* qs = base;
    unsigned* ks = base + 1280;
    unsigned* vs = base + 2560;
    unsigned* Ps = base;
    float* biasf = reinterpret_cast<float*>(sm + 2 * 3712);

    const __half* qg = g_qkvh + ((size_t)b * HEADS + h) * (NTOK * HD);
    const __half* kg = qg + (size_t)B_WIN * HEADS * NTOK * HD;
    const __half* vg = kg + (size_t)B_WIN * HEADS * NTOK * HD;

    // stage q,k row-major (zero-pad rows >= 49); v transposed [dim][token]
    for (int idx = wt; idx < 512; idx += 128) {
        const int r = idx >> 3, c = idx & 7;
        uint2 zq = make_uint2(0u, 0u), zk = zq, zv = zq;
        if (r < NTOK) {
            zq = *reinterpret_cast<const uint2*>(qg + r * 32 + c * 4);
            zk = *reinterpret_cast<const uint2*>(kg + r * 32 + c * 4);
            zv = *reinterpret_cast<const uint2*>(vg + r * 32 + c * 4);
        }
        *reinterpret_cast<uint2*>(&qs[r * 20 + c * 2]) = zq;
        *reinterpret_cast<uint2*>(&ks[r * 20 + c * 2]) = zk;
        const __half* hv = reinterpret_cast<const __half*>(&zv);
        char* vbase = reinterpret_cast<char*>(vs);
#pragma unroll
        for (int u = 0; u < 4; u++) {
            const int d = c * 4 + u;
            *reinterpret_cast<__half*>(vbase + (d * 36 + (r >> 1)) * 4 + (r & 1) * 2) = hv[u];
        }
    }
    // stage bias once for the pair (601 uint4 = 2404 floats)
    for (int i = tid; i < 601; i += 256) {
        uint4 u = *reinterpret_cast<const uint4*>(g_bias + h * 2404 + i * 4);
        *reinterpret_cast<uint4*>(&biasf[i * 4]) = u;
    }
    __syncthreads();

    const int w = wt >> 5, lane = tid & 31, g = lane >> 2, t = lane & 3;
    const int i0 = w * 16 + g, i1 = i0 + 8;

    // ---- S = q @ k^T ----
    float sacc[8][4];
#pragma unroll
    for (int j = 0; j < 8; j++)
#pragma unroll
        for (int v = 0; v < 4; v++) sacc[j][v] = 0.f;

#pragma unroll
    for (int ks2 = 0; ks2 < 2; ks2++) {
        const int kw = ks2 * 8;
        unsigned a[4] = { qs[i0 * 20 + kw + t], qs[i1 * 20 + kw + t],
                          qs[i0 * 20 + kw + t + 4], qs[i1 * 20 + kw + t + 4] };
#pragma unroll
        for (int j = 0; j < 8; j++) {
            unsigned bf[2] = { ks[(j * 8 + g) * 20 + kw + t],
                               ks[(j * 8 + g) * 20 + kw + t + 4] };
            mma16(sacc[j], a, bf);
        }
    }
    __syncthreads();   // all warps done reading qs/ks before Ps overwrite

    // ---- bias + mask + softmax ----
    float mx0 = -1e30f, mx1 = -1e30f;
#pragma unroll
    for (int j = 0; j < 8; j++) {
        const int j0 = j * 8 + 2 * t, j1 = j0 + 1;
        sacc[j][0] = (i0 < 49 && j0 < 49) ? sacc[j][0] + biasf[i0 * 49 + j0] : -1e30f;
        sacc[j][1] = (i0 < 49 && j1 < 49) ? sacc[j][1] + biasf[i0 * 49 + j1] : -1e30f;
        sacc[j][2] = (i1 < 49 && j0 < 49) ? sacc[j][2] + biasf[i1 * 49 + j0] : -1e30f;
        sacc[j][3] = (i1 < 49 && j1 < 49) ? sacc[j][3] + biasf[i1 * 49 + j1] : -1e30f;
        mx0 = fmaxf(mx0, fmaxf(sacc[j][0], sacc[j][1]));
        mx1 = fmaxf(mx1, fmaxf(sacc[j][2], sacc[j][3]));
    }
    mx0 = fmaxf(mx0, __shfl_xor_sync(0xffffffffu, mx0, 1));
    mx0 = fmaxf(mx0, __shfl_xor_sync(0xffffffffu, mx0, 2));
    mx1 = fmaxf(mx1, __shfl_xor_sync(0xffffffffu, mx1, 1));
    mx1 = fmaxf(mx1, __shfl_xor_sync(0xffffffffu, mx1, 2));

    float s0 = 0.f, s1 = 0.f;
#pragma unroll
    for (int j = 0; j < 8; j++) {
        float p0 = __expf(sacc[j][0] - mx0); sacc[j][0] = p0; s0 += p0;
        float p1 = __expf(sacc[j][1] - mx0); sacc[j][1] = p1; s0 += p1;
        float p2 = __expf(sacc[j][2] - mx1); sacc[j][2] = p2; s1 += p2;
        float p3 = __expf(sacc[j][3] - mx1); sacc[j][3] = p3; s1 += p3;
    }
    s0 += __shfl_xor_sync(0xffffffffu, s0, 1);
    s0 += __shfl_xor_sync(0xffffffffu, s0, 2);
    s1 += __shfl_xor_sync(0xffffffffu, s1, 1);
    s1 += __shfl_xor_sync(0xffffffffu, s1, 2);

    // store unnormalized P as half2 (own rows only)
#pragma unroll
    for (int j = 0; j < 8; j++) {
        Ps[i0 * 36 + j * 4 + t] = packh2(sacc[j][0], sacc[j][1]);
        Ps[i1 * 36 + j * 4 + t] = packh2(sacc[j][2], sacc[j][3]);
    }
    __syncwarp();

    // ---- O = P @ V ----
    float oacc[4][4];
#pragma unroll
    for (int nb = 0; nb < 4; nb++)
#pragma unroll
        for (int v = 0; v < 4; v++) oacc[nb][v] = 0.f;

#pragma unroll
    for (int kk = 0; kk < 4; kk++) {
        const int kw = kk * 8;
        unsigned a[4] = { Ps[i0 * 36 + kw + t], Ps[i1 * 36 + kw + t],
                          Ps[i0 * 36 + kw + t + 4], Ps[i1 * 36 + kw + t + 4] };
#pragma unroll
        for (int nb = 0; nb < 4; nb++) {
            unsigned bf[2] = { vs[(nb * 8 + g) * 36 + kw + t],
                               vs[(nb * 8 + g) * 36 + kw + t + 4] };
            mma16(oacc[nb], a, bf);
        }
    }

    const float inv0 = 1.f / s0, inv1 = 1.f / s1;
    if (i0 < 49) {
        __half* obase = g_attnh + ((size_t)b * 49 + i0) * 192 + h * 32;
#pragma unroll
        for (int nb = 0; nb < 4; nb++) {
            const int d0 = nb * 8 + 2 * t;
            *reinterpret_cast<__half2*>(obase + d0) =
                __floats2half2_rn(oacc[nb][0] * inv0, oacc[nb][1] * inv0);
        }
    }
    if (i1 < 49) {
        __half* obase = g_attnh + ((size_t)b * 49 + i1) * 192 + h * 32;
#pragma unroll
        for (int nb = 0; nb < 4; nb++) {
            const int d0 = nb * 8 + 2 * t;
            *reinterpret_cast<__half2*>(obase + d0) =
                __floats2half2_rn(oacc[nb][2] * inv1, oacc[nb][3] * inv1);
        }
    }
}

// ---------------- launch ----------------
extern "C" void kernel_launch(void* const* d_in, const int* in_sizes, int n_in,
                              void* d_out, int out_size) {
    const float* x          = (const float*)d_in[0];
    const float* qkv_w      = (const float*)d_in[1];
    const float* qkv_b      = (const float*)d_in[2];
    const float* proj_w     = (const float*)d_in[3];
    const float* proj_b     = (const float*)d_in[4];
    const float* bias_table = (const float*)d_in[5];
    const int*   rel_index  = (const int*)d_in[6];
    float* out = (float*)d_out;

    cudaFuncSetAttribute(gemm_kernel<0>, cudaFuncAttributeMaxDynamicSharedMemorySize, G_SMEM_BYTES);
    cudaFuncSetAttribute(gemm_kernel<1>, cudaFuncAttributeMaxDynamicSharedMemorySize, G_SMEM_BYTES);

    const int nx = MTOT * DIM / 4;
    cvt_kernel<0><<<(nx + 255) / 256, 256>>>(x, nx);
    cvt_kernel<1><<<(QKV_N * DIM / 4 + 255) / 256, 256>>>(qkv_w, QKV_N * DIM / 4);
    cvt_kernel<2><<<(DIM * DIM / 4 + 255) / 256, 256>>>(proj_w, DIM * DIM / 4);
    bias_kernel<<<(HEADS * NTOK * NTOK + 255) / 256, 256>>>(bias_table, rel_index);

    gemm_kernel<0><<<dim3(QKV_N / 64, MTOT / 128), 128, G_SMEM_BYTES>>>(qkv_b, nullptr);
    attn_kernel<<<B_WIN * HEADS / 2, 256>>>();
    gemm_kernel<1><<<dim3(DIM / 64, MTOT / 128), 128, G_SMEM_BYTES>>>(proj_b, out);
}

// round 8
// speedup vs baseline: 1.5151x; 1.0419x over previous
#include <cuda_runtime.h>
#include <cuda_fp16.h>
#include <cstdint>

// ---------------- problem constants ----------------
#define B_WIN 4096
#define NTOK  49
#define DIM   192
#define HEADS 6
#define HD    32
#define MTOT  (B_WIN * NTOK)            // 200704 rows
#define QKV_N (3 * DIM)                 // 576
#define SCALE 0.17677669529663687f      // 1/sqrt(32)

// ---------------- scratch (device globals: no allocs allowed) ----------------
__device__ __half g_xh    [(size_t)MTOT * DIM];                    // x in half
__device__ __half g_wqkvh [QKV_N * DIM];                           // qkv_w half
__device__ __half g_wprojh[DIM * DIM];                             // proj_w half
__device__ __half g_qkvh  [(size_t)3 * B_WIN * HEADS * NTOK * HD]; // [3,B,H,49,32]
__device__ __half g_attnh [(size_t)MTOT * DIM];                    // attn out half
__device__ __half g_biash [HEADS * 4224];                          // [H][64*66] masked bias, half

// ---------------- helpers ----------------
__device__ __forceinline__ unsigned packh2(float a, float b) {
    __half2 h = __floats2half2_rn(a, b);
    return *reinterpret_cast<unsigned*>(&h);
}

__device__ __forceinline__ void mma16(float* c, const unsigned* a, const unsigned* b) {
    asm volatile(
        "mma.sync.aligned.m16n8k16.row.col.f32.f16.f16.f32 "
        "{%0,%1,%2,%3},{%4,%5,%6,%7},{%8,%9},{%0,%1,%2,%3};\n"
        : "+f"(c[0]), "+f"(c[1]), "+f"(c[2]), "+f"(c[3])
        : "r"(a[0]), "r"(a[1]), "r"(a[2]), "r"(a[3]), "r"(b[0]), "r"(b[1]));
}

__device__ __forceinline__ uint32_t smem_u32(const void* p) {
    uint32_t a;
    asm("{ .reg .u64 t; cvta.to.shared.u64 t, %1; cvt.u32.u64 %0, t; }" : "=r"(a) : "l"(p));
    return a;
}

__device__ __forceinline__ void cpasync16(uint32_t dst, const void* src) {
    asm volatile("cp.async.ca.shared.global [%0], [%1], 16;" :: "r"(dst), "l"(src));
}
#define CP_COMMIT() asm volatile("cp.async.commit_group;" ::: "memory")
#define CP_WAIT(N)  asm volatile("cp.async.wait_group %0;" :: "n"(N) : "memory")

// ---------------- prepass: fp32 -> half converters ----------------
template <int DST>
__global__ void cvt_kernel(const float* __restrict__ src, int n4) {
    int i = blockIdx.x * blockDim.x + threadIdx.x;
    if (i >= n4) return;
    float4 v = reinterpret_cast<const float4*>(src)[i];
    uint2 u; u.x = packh2(v.x, v.y); u.y = packh2(v.z, v.w);
    __half* dst = (DST == 0) ? g_xh : (DST == 1) ? g_wqkvh : g_wprojh;
    reinterpret_cast<uint2*>(dst)[i] = u;
}

// ---------------- bias gather: half, mask baked in, [H][64 x 66] ----------------
__global__ void bias_kernel(const float* __restrict__ bias_table,
                            const int* __restrict__ rel_index) {
    int idx = blockIdx.x * blockDim.x + threadIdx.x;
    if (idx >= HEADS * 4224) return;
    const int h = idx / 4224;
    const int r = idx - h * 4224;
    const int i = r / 66, j = r - i * 66;
    float v = -60000.0f;
    if (i < NTOK && j < NTOK) v = bias_table[rel_index[i * NTOK + j] * HEADS + h];
    g_biash[idx] = __float2half_rn(v);
}

// ---------------- GEMM: C[M,Ntot] = A[M,192] @ W[Ntot,192]^T + bias ----------------
// Block tile 128x64, 4 warps (2x2), warp tile 64x32, k-tile 64.
// 2-stage cp.async double-buffered pipeline over the 3 k-tiles.
#define STG_WORDS 6912
#define G_SMEM_BYTES (2 * STG_WORDS * 4)

__device__ __forceinline__ void stage_tile(uint32_t sbase, const __half* A, const __half* W,
                                           int m0, int n0, int kb, int tid) {
#pragma unroll
    for (int k = 0; k < 8; k++) {
        const int i = tid + k * 128;
        const int r = i >> 3, c = i & 7;
        cpasync16(sbase + (uint32_t)(r * 36 + c * 4) * 4,
                  A + (size_t)(m0 + r) * 192 + kb + c * 8);
    }
#pragma unroll
    for (int k = 0; k < 4; k++) {
        const int i = tid + k * 128;
        const int r = i >> 3, c = i & 7;
        cpasync16(sbase + (uint32_t)(4608 + r * 36 + c * 4) * 4,
                  W + (size_t)(n0 + r) * 192 + kb + c * 8);
    }
}

__device__ __forceinline__ void compute_tile(const unsigned* buf, float acc[4][4][4],
                                             int wm, int wn, int g, int t) {
    const unsigned* As = buf;
    const unsigned* Bs = buf + 4608;
#pragma unroll
    for (int ks = 0; ks < 4; ks++) {
        const int kw = ks * 8;
        unsigned a[4][4], bf[4][2];
#pragma unroll
        for (int mf = 0; mf < 4; mf++) {
            const int base = (wm + mf * 16 + g) * 36 + kw + t;
            a[mf][0] = As[base];
            a[mf][1] = As[base + 8 * 36];
            a[mf][2] = As[base + 4];
            a[mf][3] = As[base + 8 * 36 + 4];
        }
#pragma unroll
        for (int nf = 0; nf < 4; nf++) {
            const int base = (wn + nf * 8 + g) * 36 + kw + t;
            bf[nf][0] = Bs[base];
            bf[nf][1] = Bs[base + 4];
        }
#pragma unroll
        for (int mf = 0; mf < 4; mf++)
#pragma unroll
            for (int nf = 0; nf < 4; nf++) mma16(acc[mf][nf], a[mf], bf[nf]);
    }
}

template <int MODE>
__global__ void __launch_bounds__(128) gemm_kernel(const float* __restrict__ bias,
                                                   float* __restrict__ Cout) {
    extern __shared__ __align__(16) unsigned sh[];
    const uint32_t sb = smem_u32(sh);

    const __half* A = (MODE == 0) ? g_xh : g_attnh;
    const __half* W = (MODE == 0) ? g_wqkvh : g_wprojh;

    const int tid = threadIdx.x;
    const int w = tid >> 5, lane = tid & 31, g = lane >> 2, t = lane & 3;
    const int wm = (w >> 1) * 64, wn = (w & 1) * 32;
    const int m0 = blockIdx.y * 128;
    const int n0 = blockIdx.x * 64;

    float acc[4][4][4];
#pragma unroll
    for (int mf = 0; mf < 4; mf++)
#pragma unroll
        for (int nf = 0; nf < 4; nf++)
#pragma unroll
            for (int v = 0; v < 4; v++) acc[mf][nf][v] = 0.f;

    stage_tile(sb,                 A, W, m0, n0, 0,   tid); CP_COMMIT();
    stage_tile(sb + STG_WORDS * 4, A, W, m0, n0, 64,  tid); CP_COMMIT();

    CP_WAIT(1); __syncthreads();
    compute_tile(sh, acc, wm, wn, g, t);
    __syncthreads();
    stage_tile(sb, A, W, m0, n0, 128, tid); CP_COMMIT();

    CP_WAIT(1); __syncthreads();
    compute_tile(sh + STG_WORDS, acc, wm, wn, g, t);
    __syncthreads();

    CP_WAIT(0); __syncthreads();
    compute_tile(sh, acc, wm, wn, g, t);

    // ---- epilogue ----
#pragma unroll
    for (int mf = 0; mf < 4; mf++) {
        const int ma = m0 + wm + mf * 16 + g;
        const int mb = ma + 8;
        const int wa = ma / 49, ta = ma - wa * 49;
        const int wb = mb / 49, tb = mb - wb * 49;
#pragma unroll
        for (int nf = 0; nf < 4; nf++) {
            const int gc = n0 + wn + nf * 8 + 2 * t;
            float2 bb = __ldg(reinterpret_cast<const float2*>(bias + gc));
            float v00 = acc[mf][nf][0] + bb.x;
            float v01 = acc[mf][nf][1] + bb.y;
            float v10 = acc[mf][nf][2] + bb.x;
            float v11 = acc[mf][nf][3] + bb.y;
            if (MODE == 0) {
                if (gc < 192) { v00 *= SCALE; v01 *= SCALE; v10 *= SCALE; v11 *= SCALE; }
                const int s  = gc / 192;
                const int hh = (gc - s * 192) >> 5;
                const int d  = gc & 31;
                __half2* pa = reinterpret_cast<__half2*>(
                    g_qkvh + ((((size_t)s * B_WIN + wa) * HEADS + hh) * NTOK + ta) * HD + d);
                __half2* pb = reinterpret_cast<__half2*>(
                    g_qkvh + ((((size_t)s * B_WIN + wb) * HEADS + hh) * NTOK + tb) * HD + d);
                *pa = __floats2half2_rn(v00, v01);
                *pb = __floats2half2_rn(v10, v11);
            } else {
                *reinterpret_cast<float2*>(Cout + (size_t)ma * DIM + gc) = make_float2(v00, v01);
                *reinterpret_cast<float2*>(Cout + (size_t)mb * DIM + gc) = make_float2(v10, v11);
            }
        }
    }
}

// ---------------- attention: one block per (window-pair, head), 256 threads ----------------
// Per-window region (3840 words): qs 64x20 | ks 64x20 | vs 64x20 (all row-major, stride 20).
// Shared masked-bias (2112 words = 64x66 half) staged once for both windows.
// P stays in registers (S-fragment == A-fragment); V loaded via ldmatrix.x4.trans.
__global__ void __launch_bounds__(256) attn_kernel() {
    __shared__ __align__(16) unsigned sm[2 * 3840 + 2112];

    const int tid = threadIdx.x;
    const int half_id = tid >> 7;       // window select within pair
    const int wt = tid & 127;

    const int bh2 = blockIdx.x;
    const int h = bh2 % HEADS;
    const int wp = bh2 / HEADS;
    const int b = wp * 2 + half_id;

    unsigned* base = sm + half_id * 3840;
    unsigned* qs = base;
    unsigned* ks = base + 1280;
    unsigned* vs = base + 2560;
    unsigned* biassm = sm + 2 * 3840;

    const __half* qg = g_qkvh + ((size_t)b * HEADS + h) * (NTOK * HD);
    const __half* kg = qg + (size_t)B_WIN * HEADS * NTOK * HD;
    const __half* vg = kg + (size_t)B_WIN * HEADS * NTOK * HD;

    // stage q,k,v row-major (zero-pad rows >= 49)
    for (int idx = wt; idx < 512; idx += 128) {
        const int r = idx >> 3, c = idx & 7;
        uint2 zq = make_uint2(0u, 0u), zk = zq, zv = zq;
        if (r < NTOK) {
            zq = *reinterpret_cast<const uint2*>(qg + r * 32 + c * 4);
            zk = *reinterpret_cast<const uint2*>(kg + r * 32 + c * 4);
            zv = *reinterpret_cast<const uint2*>(vg + r * 32 + c * 4);
        }
        *reinterpret_cast<uint2*>(&qs[r * 20 + c * 2]) = zq;
        *reinterpret_cast<uint2*>(&ks[r * 20 + c * 2]) = zk;
        *reinterpret_cast<uint2*>(&vs[r * 20 + c * 2]) = zv;
    }
    // stage masked bias once for the pair (528 uint4 = 2112 words)
    {
        const uint4* src = reinterpret_cast<const uint4*>(g_biash + h * 4224);
        for (int i = tid; i < 528; i += 256)
            reinterpret_cast<uint4*>(biassm)[i] = src[i];
    }
    __syncthreads();

    const int w = wt >> 5, lane = tid & 31, g = lane >> 2, t = lane & 3;
    const int i0 = w * 16 + g, i1 = i0 + 8;

    // ---- S = q @ k^T ----
    float sacc[8][4];
#pragma unroll
    for (int j = 0; j < 8; j++)
#pragma unroll
        for (int v = 0; v < 4; v++) sacc[j][v] = 0.f;

#pragma unroll
    for (int ks2 = 0; ks2 < 2; ks2++) {
        const int kw = ks2 * 8;
        unsigned a[4] = { qs[i0 * 20 + kw + t], qs[i1 * 20 + kw + t],
                          qs[i0 * 20 + kw + t + 4], qs[i1 * 20 + kw + t + 4] };
#pragma unroll
        for (int j = 0; j < 8; j++) {
            unsigned bf[2] = { ks[(j * 8 + g) * 20 + kw + t],
                               ks[(j * 8 + g) * 20 + kw + t + 4] };
            mma16(sacc[j], a, bf);
        }
    }

    // ---- masked bias add + softmax (no predicates: mask baked into bias) ----
    const __half2* bh2p = reinterpret_cast<const __half2*>(biassm);
    float mx0 = -1e30f, mx1 = -1e30f;
#pragma unroll
    for (int j = 0; j < 8; j++) {
        float2 b0 = __half22float2(bh2p[i0 * 33 + j * 4 + t]);
        float2 b1 = __half22float2(bh2p[i1 * 33 + j * 4 + t]);
        sacc[j][0] += b0.x; sacc[j][1] += b0.y;
        sacc[j][2] += b1.x; sacc[j][3] += b1.y;
        mx0 = fmaxf(mx0, fmaxf(sacc[j][0], sacc[j][1]));
        mx1 = fmaxf(mx1, fmaxf(sacc[j][2], sacc[j][3]));
    }
    mx0 = fmaxf(mx0, __shfl_xor_sync(0xffffffffu, mx0, 1));
    mx0 = fmaxf(mx0, __shfl_xor_sync(0xffffffffu, mx0, 2));
    mx1 = fmaxf(mx1, __shfl_xor_sync(0xffffffffu, mx1, 1));
    mx1 = fmaxf(mx1, __shfl_xor_sync(0xffffffffu, mx1, 2));

    float s0 = 0.f, s1 = 0.f;
#pragma unroll
    for (int j = 0; j < 8; j++) {
        float p0 = __expf(sacc[j][0] - mx0); sacc[j][0] = p0; s0 += p0;
        float p1 = __expf(sacc[j][1] - mx0); sacc[j][1] = p1; s0 += p1;
        float p2 = __expf(sacc[j][2] - mx1); sacc[j][2] = p2; s1 += p2;
        float p3 = __expf(sacc[j][3] - mx1); sacc[j][3] = p3; s1 += p3;
    }
    s0 += __shfl_xor_sync(0xffffffffu, s0, 1);
    s0 += __shfl_xor_sync(0xffffffffu, s0, 2);
    s1 += __shfl_xor_sync(0xffffffffu, s1, 1);
    s1 += __shfl_xor_sync(0xffffffffu, s1, 2);

    // ---- O = P @ V : P直接 from registers, V via ldmatrix.x4.trans ----
    const uint32_t vsb = smem_u32(vs);
    const uint32_t row_off = (uint32_t)((((lane & 7) + ((lane >> 3) & 1) * 8) * 20) * 4);
    const uint32_t nb_hi = (uint32_t)(lane >> 4);   // 0 for lanes 0-15, 1 for 16-31

    float oacc[4][4];
#pragma unroll
    for (int nb = 0; nb < 4; nb++)
#pragma unroll
        for (int v = 0; v < 4; v++) oacc[nb][v] = 0.f;

#pragma unroll
    for (int kk = 0; kk < 4; kk++) {
        unsigned a[4] = { packh2(sacc[2 * kk][0],     sacc[2 * kk][1]),
                          packh2(sacc[2 * kk][2],     sacc[2 * kk][3]),
                          packh2(sacc[2 * kk + 1][0], sacc[2 * kk + 1][1]),
                          packh2(sacc[2 * kk + 1][2], sacc[2 * kk + 1][3]) };
#pragma unroll
        for (int hn = 0; hn < 2; hn++) {
            const uint32_t nbb = 2 * hn + nb_hi;
            const uint32_t addr = vsb + (uint32_t)(kk * 1280) + row_off + nbb * 16;
            uint32_t r0, r1, r2, r3;
            asm volatile("ldmatrix.sync.aligned.m8n8.x4.trans.shared.b16 {%0,%1,%2,%3}, [%4];"
                         : "=r"(r0), "=r"(r1), "=r"(r2), "=r"(r3) : "r"(addr));
            unsigned b0[2] = { r0, r1 };
            unsigned b1[2] = { r2, r3 };
            mma16(oacc[2 * hn], a, b0);
            mma16(oacc[2 * hn + 1], a, b1);
        }
    }

    const float inv0 = 1.f / s0, inv1 = 1.f / s1;
    if (i0 < 49) {
        __half* obase = g_attnh + ((size_t)b * 49 + i0) * 192 + h * 32;
#pragma unroll
        for (int nb = 0; nb < 4; nb++) {
            const int d0 = nb * 8 + 2 * t;
            *reinterpret_cast<__half2*>(obase + d0) =
                __floats2half2_rn(oacc[nb][0] * inv0, oacc[nb][1] * inv0);
        }
    }
    if (i1 < 49) {
        __half* obase = g_attnh + ((size_t)b * 49 + i1) * 192 + h * 32;
#pragma unroll
        for (int nb = 0; nb < 4; nb++) {
            const int d0 = nb * 8 + 2 * t;
            *reinterpret_cast<__half2*>(obase + d0) =
                __floats2half2_rn(oacc[nb][2] * inv1, oacc[nb][3] * inv1);
        }
    }
}

// ---------------- launch ----------------
extern "C" void kernel_launch(void* const* d_in, const int* in_sizes, int n_in,
                              void* d_out, int out_size) {
    const float* x          = (const float*)d_in[0];
    const float* qkv_w      = (const float*)d_in[1];
    const float* qkv_b      = (const float*)d_in[2];
    const float* proj_w     = (const float*)d_in[3];
    const float* proj_b     = (const float*)d_in[4];
    const float* bias_table = (const float*)d_in[5];
    const int*   rel_index  = (const int*)d_in[6];
    float* out = (float*)d_out;

    cudaFuncSetAttribute(gemm_kernel<0>, cudaFuncAttributeMaxDynamicSharedMemorySize, G_SMEM_BYTES);
    cudaFuncSetAttribute(gemm_kernel<1>, cudaFuncAttributeMaxDynamicSharedMemorySize, G_SMEM_BYTES);

    const int nx = MTOT * DIM / 4;
    cvt_kernel<0><<<(nx + 255) / 256, 256>>>(x, nx);
    cvt_kernel<1><<<(QKV_N * DIM / 4 + 255) / 256, 256>>>(qkv_w, QKV_N * DIM / 4);
    cvt_kernel<2><<<(DIM * DIM / 4 + 255) / 256, 256>>>(proj_w, DIM * DIM / 4);
    bias_kernel<<<(HEADS * 4224 + 255) / 256, 256>>>(bias_table, rel_index);

    gemm_kernel<0><<<dim3(QKV_N / 64, MTOT / 128), 128, G_SMEM_BYTES>>>(qkv_b, nullptr);
    attn_kernel<<<B_WIN * HEADS / 2, 256>>>();
    gemm_kernel<1><<<dim3(DIM / 64, MTOT / 128), 128, G_SMEM_BYTES>>>(proj_b, out);
}

// round 9
// speedup vs baseline: 1.6466x; 1.0868x over previous
#include <cuda_runtime.h>
#include <cuda_fp16.h>
#include <cstdint>

// ---------------- problem constants ----------------
#define B_WIN 4096
#define NTOK  49
#define DIM   192
#define HEADS 6
#define HD    32
#define MTOT  (B_WIN * NTOK)            // 200704 rows
#define QKV_N (3 * DIM)                 // 576
#define SCALE 0.17677669529663687f      // 1/sqrt(32)

// ---------------- scratch (device globals: no allocs allowed) ----------------
__device__ __half g_xh    [(size_t)MTOT * DIM];                    // x in half
__device__ __half g_wqkvh [QKV_N * DIM];                           // qkv_w half
__device__ __half g_wprojh[DIM * DIM];                             // proj_w half
__device__ __half g_qkvh  [(size_t)3 * B_WIN * HEADS * NTOK * HD]; // [3,B,H,49,32]
__device__ __half g_attnh [(size_t)MTOT * DIM];                    // attn out half
__device__ __half g_biash [HEADS * 4224];                          // [H][64*66] masked bias, half

// ---------------- helpers ----------------
__device__ __forceinline__ unsigned packh2(float a, float b) {
    __half2 h = __floats2half2_rn(a, b);
    return *reinterpret_cast<unsigned*>(&h);
}

__device__ __forceinline__ void mma16(float* c, const unsigned* a, const unsigned* b) {
    asm volatile(
        "mma.sync.aligned.m16n8k16.row.col.f32.f16.f16.f32 "
        "{%0,%1,%2,%3},{%4,%5,%6,%7},{%8,%9},{%0,%1,%2,%3};\n"
        : "+f"(c[0]), "+f"(c[1]), "+f"(c[2]), "+f"(c[3])
        : "r"(a[0]), "r"(a[1]), "r"(a[2]), "r"(a[3]), "r"(b[0]), "r"(b[1]));
}

__device__ __forceinline__ uint32_t smem_u32(const void* p) {
    uint32_t a;
    asm("{ .reg .u64 t; cvta.to.shared.u64 t, %1; cvt.u32.u64 %0, t; }" : "=r"(a) : "l"(p));
    return a;
}

__device__ __forceinline__ void cpasync16(uint32_t dst, const void* src) {
    asm volatile("cp.async.ca.shared.global [%0], [%1], 16;" :: "r"(dst), "l"(src));
}
#define CP_COMMIT() asm volatile("cp.async.commit_group;" ::: "memory")
#define CP_WAIT(N)  asm volatile("cp.async.wait_group %0;" :: "n"(N) : "memory")

// ---------------- prepass: fp32 -> half converters ----------------
template <int DST>
__global__ void cvt_kernel(const float* __restrict__ src, int n4) {
    int i = blockIdx.x * blockDim.x + threadIdx.x;
    if (i >= n4) return;
    float4 v = reinterpret_cast<const float4*>(src)[i];
    uint2 u; u.x = packh2(v.x, v.y); u.y = packh2(v.z, v.w);
    __half* dst = (DST == 0) ? g_xh : (DST == 1) ? g_wqkvh : g_wprojh;
    reinterpret_cast<uint2*>(dst)[i] = u;
}

// ---------------- bias gather: half, mask baked in, [H][64 x 66] ----------------
__global__ void bias_kernel(const float* __restrict__ bias_table,
                            const int* __restrict__ rel_index) {
    int idx = blockIdx.x * blockDim.x + threadIdx.x;
    if (idx >= HEADS * 4224) return;
    const int h = idx / 4224;
    const int r = idx - h * 4224;
    const int i = r / 66, j = r - i * 66;
    float v = -60000.0f;
    if (i < NTOK && j < NTOK) v = bias_table[rel_index[i * NTOK + j] * HEADS + h];
    g_biash[idx] = __float2half_rn(v);
}

// ---------------- GEMM: C[M,Ntot] = A[M,192] @ W[Ntot,192]^T + bias ----------------
// Block tile 128x96, 4 warps (2x2), warp tile 64x48, k-tile 64.
// 2-stage cp.async double-buffered pipeline over the 3 k-tiles.
// Stage layout (words): A 128x36 (=4608) | B 96x36 (=3456); stage = 8064 words.
#define STG_WORDS 8064
#define G_SMEM_BYTES (2 * STG_WORDS * 4)

__device__ __forceinline__ void stage_tile(uint32_t sbase, const __half* A, const __half* W,
                                           int m0, int n0, int kb, int tid) {
#pragma unroll
    for (int k = 0; k < 8; k++) {
        const int i = tid + k * 128;
        const int r = i >> 3, c = i & 7;
        cpasync16(sbase + (uint32_t)(r * 36 + c * 4) * 4,
                  A + (size_t)(m0 + r) * 192 + kb + c * 8);
    }
#pragma unroll
    for (int k = 0; k < 6; k++) {
        const int i = tid + k * 128;
        const int r = i >> 3, c = i & 7;
        cpasync16(sbase + (uint32_t)(4608 + r * 36 + c * 4) * 4,
                  W + (size_t)(n0 + r) * 192 + kb + c * 8);
    }
}

__device__ __forceinline__ void compute_tile(const unsigned* buf, float acc[4][6][4],
                                             int wm, int wn, int g, int t) {
    const unsigned* As = buf;
    const unsigned* Bs = buf + 4608;
#pragma unroll
    for (int ks = 0; ks < 4; ks++) {
        const int kw = ks * 8;
        unsigned a[4][4], bf[6][2];
#pragma unroll
        for (int mf = 0; mf < 4; mf++) {
            const int base = (wm + mf * 16 + g) * 36 + kw + t;
            a[mf][0] = As[base];
            a[mf][1] = As[base + 8 * 36];
            a[mf][2] = As[base + 4];
            a[mf][3] = As[base + 8 * 36 + 4];
        }
#pragma unroll
        for (int nf = 0; nf < 6; nf++) {
            const int base = (wn + nf * 8 + g) * 36 + kw + t;
            bf[nf][0] = Bs[base];
            bf[nf][1] = Bs[base + 4];
        }
#pragma unroll
        for (int mf = 0; mf < 4; mf++)
#pragma unroll
            for (int nf = 0; nf < 6; nf++) mma16(acc[mf][nf], a[mf], bf[nf]);
    }
}

template <int MODE>
__global__ void __launch_bounds__(128) gemm_kernel(const float* __restrict__ bias,
                                                   float* __restrict__ Cout) {
    extern __shared__ __align__(16) unsigned sh[];
    const uint32_t sb = smem_u32(sh);

    const __half* A = (MODE == 0) ? g_xh : g_attnh;
    const __half* W = (MODE == 0) ? g_wqkvh : g_wprojh;

    const int tid = threadIdx.x;
    const int w = tid >> 5, lane = tid & 31, g = lane >> 2, t = lane & 3;
    const int wm = (w >> 1) * 64, wn = (w & 1) * 48;
    const int m0 = blockIdx.y * 128;
    const int n0 = blockIdx.x * 96;

    float acc[4][6][4];
#pragma unroll
    for (int mf = 0; mf < 4; mf++)
#pragma unroll
        for (int nf = 0; nf < 6; nf++)
#pragma unroll
            for (int v = 0; v < 4; v++) acc[mf][nf][v] = 0.f;

    stage_tile(sb,                 A, W, m0, n0, 0,   tid); CP_COMMIT();
    stage_tile(sb + STG_WORDS * 4, A, W, m0, n0, 64,  tid); CP_COMMIT();

    CP_WAIT(1); __syncthreads();
    compute_tile(sh, acc, wm, wn, g, t);
    __syncthreads();
    stage_tile(sb, A, W, m0, n0, 128, tid); CP_COMMIT();

    CP_WAIT(1); __syncthreads();
    compute_tile(sh + STG_WORDS, acc, wm, wn, g, t);
    __syncthreads();

    CP_WAIT(0); __syncthreads();
    compute_tile(sh, acc, wm, wn, g, t);

    // ---- epilogue ----
#pragma unroll
    for (int mf = 0; mf < 4; mf++) {
        const int ma = m0 + wm + mf * 16 + g;
        const int mb = ma + 8;
        const int wa = ma / 49, ta = ma - wa * 49;
        const int wb = mb / 49, tb = mb - wb * 49;
#pragma unroll
        for (int nf = 0; nf < 6; nf++) {
            const int gc = n0 + wn + nf * 8 + 2 * t;
            float2 bb = __ldg(reinterpret_cast<const float2*>(bias + gc));
            float v00 = acc[mf][nf][0] + bb.x;
            float v01 = acc[mf][nf][1] + bb.y;
            float v10 = acc[mf][nf][2] + bb.x;
            float v11 = acc[mf][nf][3] + bb.y;
            if (MODE == 0) {
                if (gc < 192) { v00 *= SCALE; v01 *= SCALE; v10 *= SCALE; v11 *= SCALE; }
                const int s  = gc / 192;
                const int hh = (gc - s * 192) >> 5;
                const int d  = gc & 31;
                __half2* pa = reinterpret_cast<__half2*>(
                    g_qkvh + ((((size_t)s * B_WIN + wa) * HEADS + hh) * NTOK + ta) * HD + d);
                __half2* pb = reinterpret_cast<__half2*>(
                    g_qkvh + ((((size_t)s * B_WIN + wb) * HEADS + hh) * NTOK + tb) * HD + d);
                *pa = __floats2half2_rn(v00, v01);
                *pb = __floats2half2_rn(v10, v11);
            } else {
                *reinterpret_cast<float2*>(Cout + (size_t)ma * DIM + gc) = make_float2(v00, v01);
                *reinterpret_cast<float2*>(Cout + (size_t)mb * DIM + gc) = make_float2(v10, v11);
            }
        }
    }
}

// ---------------- attention: one block per (window-pair, head), 256 threads ----------------
// Per-window region (3840 words): qs 64x20 | ks 64x20 | vs 64x20 (all row-major, stride 20).
// Shared masked-bias (2112 words = 64x66 half) staged once for both windows.
// P stays in registers (S-fragment == A-fragment); V loaded via ldmatrix.x4.trans.
__global__ void __launch_bounds__(256) attn_kernel() {
    __shared__ __align__(16) unsigned sm[2 * 3840 + 2112];

    const int tid = threadIdx.x;
    const int half_id = tid >> 7;       // window select within pair
    const int wt = tid & 127;

    const int bh2 = blockIdx.x;
    const int h = bh2 % HEADS;
    const int wp = bh2 / HEADS;
    const int b = wp * 2 + half_id;

    unsigned* base = sm + half_id * 3840;
    unsigned* qs = base;
    unsigned* ks = base + 1280;
    unsigned* vs = base + 2560;
    unsigned* biassm = sm + 2 * 3840;

    const __half* qg = g_qkvh + ((size_t)b * HEADS + h) * (NTOK * HD);
    const __half* kg = qg + (size_t)B_WIN * HEADS * NTOK * HD;
    const __half* vg = kg + (size_t)B_WIN * HEADS * NTOK * HD;

    // stage q,k,v row-major (zero-pad rows >= 49)
    for (int idx = wt; idx < 512; idx += 128) {
        const int r = idx >> 3, c = idx & 7;
        uint2 zq = make_uint2(0u, 0u), zk = zq, zv = zq;
        if (r < NTOK) {
            zq = *reinterpret_cast<const uint2*>(qg + r * 32 + c * 4);
            zk = *reinterpret_cast<const uint2*>(kg + r * 32 + c * 4);
            zv = *reinterpret_cast<const uint2*>(vg + r * 32 + c * 4);
        }
        *reinterpret_cast<uint2*>(&qs[r * 20 + c * 2]) = zq;
        *reinterpret_cast<uint2*>(&ks[r * 20 + c * 2]) = zk;
        *reinterpret_cast<uint2*>(&vs[r * 20 + c * 2]) = zv;
    }
    // stage masked bias once for the pair (528 uint4 = 2112 words)
    {
        const uint4* src = reinterpret_cast<const uint4*>(g_biash + h * 4224);
        for (int i = tid; i < 528; i += 256)
            reinterpret_cast<uint4*>(biassm)[i] = src[i];
    }
    __syncthreads();

    const int w = wt >> 5, lane = tid & 31, g = lane >> 2, t = lane & 3;
    const int i0 = w * 16 + g, i1 = i0 + 8;

    // ---- S = q @ k^T ----
    float sacc[8][4];
#pragma unroll
    for (int j = 0; j < 8; j++)
#pragma unroll
        for (int v = 0; v < 4; v++) sacc[j][v] = 0.f;

#pragma unroll
    for (int ks2 = 0; ks2 < 2; ks2++) {
        const int kw = ks2 * 8;
        unsigned a[4] = { qs[i0 * 20 + kw + t], qs[i1 * 20 + kw + t],
                          qs[i0 * 20 + kw + t + 4], qs[i1 * 20 + kw + t + 4] };
#pragma unroll
        for (int j = 0; j < 8; j++) {
            unsigned bf[2] = { ks[(j * 8 + g) * 20 + kw + t],
                               ks[(j * 8 + g) * 20 + kw + t + 4] };
            mma16(sacc[j], a, bf);
        }
    }

    // ---- masked bias add + softmax (no predicates: mask baked into bias) ----
    const __half2* bh2p = reinterpret_cast<const __half2*>(biassm);
    float mx0 = -1e30f, mx1 = -1e30f;
#pragma unroll
    for (int j = 0; j < 8; j++) {
        float2 b0 = __half22float2(bh2p[i0 * 33 + j * 4 + t]);
        float2 b1 = __half22float2(bh2p[i1 * 33 + j * 4 + t]);
        sacc[j][0] += b0.x; sacc[j][1] += b0.y;
        sacc[j][2] += b1.x; sacc[j][3] += b1.y;
        mx0 = fmaxf(mx0, fmaxf(sacc[j][0], sacc[j][1]));
        mx1 = fmaxf(mx1, fmaxf(sacc[j][2], sacc[j][3]));
    }
    mx0 = fmaxf(mx0, __shfl_xor_sync(0xffffffffu, mx0, 1));
    mx0 = fmaxf(mx0, __shfl_xor_sync(0xffffffffu, mx0, 2));
    mx1 = fmaxf(mx1, __shfl_xor_sync(0xffffffffu, mx1, 1));
    mx1 = fmaxf(mx1, __shfl_xor_sync(0xffffffffu, mx1, 2));

    float s0 = 0.f, s1 = 0.f;
#pragma unroll
    for (int j = 0; j < 8; j++) {
        float p0 = __expf(sacc[j][0] - mx0); sacc[j][0] = p0; s0 += p0;
        float p1 = __expf(sacc[j][1] - mx0); sacc[j][1] = p1; s0 += p1;
        float p2 = __expf(sacc[j][2] - mx1); sacc[j][2] = p2; s1 += p2;
        float p3 = __expf(sacc[j][3] - mx1); sacc[j][3] = p3; s1 += p3;
    }
    s0 += __shfl_xor_sync(0xffffffffu, s0, 1);
    s0 += __shfl_xor_sync(0xffffffffu, s0, 2);
    s1 += __shfl_xor_sync(0xffffffffu, s1, 1);
    s1 += __shfl_xor_sync(0xffffffffu, s1, 2);

    // ---- O = P @ V : P from registers, V via ldmatrix.x4.trans ----
    const uint32_t vsb = smem_u32(vs);
    const uint32_t row_off = (uint32_t)((((lane & 7) + ((lane >> 3) & 1) * 8) * 20) * 4);
    const uint32_t nb_hi = (uint32_t)(lane >> 4);   // 0 for lanes 0-15, 1 for 16-31

    float oacc[4][4];
#pragma unroll
    for (int nb = 0; nb < 4; nb++)
#pragma unroll
        for (int v = 0; v < 4; v++) oacc[nb][v] = 0.f;

#pragma unroll
    for (int kk = 0; kk < 4; kk++) {
        unsigned a[4] = { packh2(sacc[2 * kk][0],     sacc[2 * kk][1]),
                          packh2(sacc[2 * kk][2],     sacc[2 * kk][3]),
                          packh2(sacc[2 * kk + 1][0], sacc[2 * kk + 1][1]),
                          packh2(sacc[2 * kk + 1][2], sacc[2 * kk + 1][3]) };
#pragma unroll
        for (int hn = 0; hn < 2; hn++) {
            const uint32_t nbb = 2 * hn + nb_hi;
            const uint32_t addr = vsb + (uint32_t)(kk * 1280) + row_off + nbb * 16;
            uint32_t r0, r1, r2, r3;
            asm volatile("ldmatrix.sync.aligned.m8n8.x4.trans.shared.b16 {%0,%1,%2,%3}, [%4];"
                         : "=r"(r0), "=r"(r1), "=r"(r2), "=r"(r3) : "r"(addr));
            unsigned b0[2] = { r0, r1 };
            unsigned b1[2] = { r2, r3 };
            mma16(oacc[2 * hn], a, b0);
            mma16(oacc[2 * hn + 1], a, b1);
        }
    }

    const float inv0 = 1.f / s0, inv1 = 1.f / s1;
    if (i0 < 49) {
        __half* obase = g_attnh + ((size_t)b * 49 + i0) * 192 + h * 32;
#pragma unroll
        for (int nb = 0; nb < 4; nb++) {
            const int d0 = nb * 8 + 2 * t;
            *reinterpret_cast<__half2*>(obase + d0) =
                __floats2half2_rn(oacc[nb][0] * inv0, oacc[nb][1] * inv0);
        }
    }
    if (i1 < 49) {
        __half* obase = g_attnh + ((size_t)b * 49 + i1) * 192 + h * 32;
#pragma unroll
        for (int nb = 0; nb < 4; nb++) {
            const int d0 = nb * 8 + 2 * t;
            *reinterpret_cast<__half2*>(obase + d0) =
                __floats2half2_rn(oacc[nb][2] * inv1, oacc[nb][3] * inv1);
        }
    }
}

// ---------------- launch ----------------
extern "C" void kernel_launch(void* const* d_in, const int* in_sizes, int n_in,
                              void* d_out, int out_size) {
    const float* x          = (const float*)d_in[0];
    const float* qkv_w      = (const float*)d_in[1];
    const float* qkv_b      = (const float*)d_in[2];
    const float* proj_w     = (const float*)d_in[3];
    const float* proj_b     = (const float*)d_in[4];
    const float* bias_table = (const float*)d_in[5];
    const int*   rel_index  = (const int*)d_in[6];
    float* out = (float*)d_out;

    cudaFuncSetAttribute(gemm_kernel<0>, cudaFuncAttributeMaxDynamicSharedMemorySize, G_SMEM_BYTES);
    cudaFuncSetAttribute(gemm_kernel<1>, cudaFuncAttributeMaxDynamicSharedMemorySize, G_SMEM_BYTES);

    const int nx = MTOT * DIM / 4;
    cvt_kernel<0><<<(nx + 255) / 256, 256>>>(x, nx);
    cvt_kernel<1><<<(QKV_N * DIM / 4 + 255) / 256, 256>>>(qkv_w, QKV_N * DIM / 4);
    cvt_kernel<2><<<(DIM * DIM / 4 + 255) / 256, 256>>>(proj_w, DIM * DIM / 4);
    bias_kernel<<<(HEADS * 4224 + 255) / 256, 256>>>(bias_table, rel_index);

    gemm_kernel<0><<<dim3(QKV_N / 96, MTOT / 128), 128, G_SMEM_BYTES>>>(qkv_b, nullptr);
    attn_kernel<<<B_WIN * HEADS / 2, 256>>>();
    gemm_kernel<1><<<dim3(DIM / 96, MTOT / 128), 128, G_SMEM_BYTES>>>(proj_b, out);
}